// round 3
// baseline (speedup 1.0000x reference)
#include <cuda_runtime.h>
#include <cstdint>

#define ND 128
#define ED 64
#define NH 4
#define HD 32
#define MAX_NODES 50000
#define MAX_EDGES 600000

typedef unsigned long long ull;

// ---------------- scratch (static device globals) ---------------------------
__device__ __align__(16) float g_h[MAX_NODES * ND];     // projected nodes
__device__ __align__(16) float g_s1[MAX_NODES * NH];    // h . a[:, 0:32]
__device__ __align__(16) float g_s2[MAX_NODES * NH];    // h . a[:, 32:64]
__device__ __align__(16) float g_att[MAX_EDGES * NH];   // leaky-relu scores
__device__ __align__(16) float g_v[NH * ED];            // folded edge attn vec
__device__ int g_cnt[MAX_NODES + 1];                    // degree histogram
__device__ int g_off[MAX_NODES + 1];                    // CSR row offsets
__device__ int g_head[MAX_NODES];                       // scatter cursors
__device__ __align__(8) int2 g_csr[MAX_EDGES];          // {edge id, src} per tgt

#define FMA2(d, a, b) \
    asm("fma.rn.f32x2 %0, %1, %2, %0;" : "+l"(d) : "l"(a), "l"(b))
#define PACKDUP(d, f) \
    asm("mov.b64 %0, {%1, %1};" : "=l"(d) : "r"(__float_as_uint(f)))

// ---------------- launch 1: zero counts + fold W_edge into attn vector ------
__global__ void kern_init(const float* __restrict__ W_edge,
                          const float* __restrict__ a, int n) {
    if ((int)blockIdx.x < (int)gridDim.x - 1) {
        int i = blockIdx.x * 256 + threadIdx.x;
        if (i <= n) g_cnt[i] = 0;
    } else {
        int t = threadIdx.x;  // 256 == NH*ED
        int h = t >> 6, k = t & 63;
        float s = 0.f;
#pragma unroll
        for (int d = 0; d < HD; d++)
            s += W_edge[(h * HD + d) * ED + k] * __ldg(&a[h * 3 * HD + 2 * HD + d]);
        g_v[h * ED + k] = s;
    }
}

// ---------------- launch 2: degree histogram ---------------------------------
__global__ void kern_hist(const int* __restrict__ ei, int n_edges) {
    int e = blockIdx.x * blockDim.x + threadIdx.x;
    if (e < n_edges) atomicAdd(&g_cnt[ei[n_edges + e]], 1);
}

// ---------------- launch 3: single-block exclusive scan ----------------------
__global__ void kern_scan(int n, int n_edges) {
    __shared__ int wsums[32];
    int t = threadIdx.x;  // 1024
    int items = (n + 1023) >> 10;
    int base = t * items;
    int lim = min(items, n - base);

    int sum = 0;
    for (int i = 0; i < lim; i++) sum += g_cnt[base + i];

    int lane = t & 31, w = t >> 5;
    int inc = sum;
#pragma unroll
    for (int o = 1; o < 32; o <<= 1) {
        int x = __shfl_up_sync(0xffffffffu, inc, o);
        if (lane >= o) inc += x;
    }
    if (lane == 31) wsums[w] = inc;
    __syncthreads();
    if (w == 0) {
        int v = wsums[lane];
        int winc = v;
#pragma unroll
        for (int o = 1; o < 32; o <<= 1) {
            int x = __shfl_up_sync(0xffffffffu, winc, o);
            if (lane >= o) winc += x;
        }
        wsums[lane] = winc - v;
    }
    __syncthreads();
    int run = inc - sum + wsums[w];
    for (int i = 0; i < lim; i++) {
        int idx = base + i;
        g_off[idx] = run;
        g_head[idx] = run;
        run += g_cnt[idx];
    }
    if (t == 0) g_off[n] = n_edges;
}

// ---------------- launch 4 (profiled): h = X @ W^T f32x2 GEMM + s1/s2 -------
__global__ void kern_gemm(const float* __restrict__ X, const float* __restrict__ W,
                          const float* __restrict__ a, int n) {
    extern __shared__ float sm[];
    float* Ws = sm;                  // [128 k][132 cols]
    float* At = sm + 128 * 132;     // [128 k][66 rows] (k-major)
    int t = threadIdx.x;

    for (int i = t; i < ND * ND; i += 256) {
        int j = i >> 7, k = i & 127;
        Ws[k * 132 + j] = W[i];
    }
    int row0 = blockIdx.x * 64;
    for (int i = t; i < 64 * ND; i += 256) {
        int r = i >> 7, k = i & 127;
        int gr = row0 + r;
        At[k * 66 + r] = (gr < n) ? X[(size_t)gr * ND + k] : 0.f;
    }
    __syncthreads();

    int tx = t & 31, ty = t >> 5;
    ull acc[4][4];
#pragma unroll
    for (int p = 0; p < 4; p++)
#pragma unroll
        for (int c = 0; c < 4; c++) acc[p][c] = 0ULL;

    const ull* ab = (const ull*)At + ty * 4;  // + k*33 per step
    const float* wb = &Ws[tx * 4];

#pragma unroll 4
    for (int k = 0; k < ND; k++) {
        float4 wv = *(const float4*)(wb + k * 132);
        ull w0, w1, w2, w3;
        PACKDUP(w0, wv.x); PACKDUP(w1, wv.y); PACKDUP(w2, wv.z); PACKDUP(w3, wv.w);
        ull a0 = ab[k * 33 + 0];
        ull a1 = ab[k * 33 + 1];
        ull a2 = ab[k * 33 + 2];
        ull a3 = ab[k * 33 + 3];
        FMA2(acc[0][0], a0, w0); FMA2(acc[0][1], a0, w1);
        FMA2(acc[0][2], a0, w2); FMA2(acc[0][3], a0, w3);
        FMA2(acc[1][0], a1, w0); FMA2(acc[1][1], a1, w1);
        FMA2(acc[1][2], a1, w2); FMA2(acc[1][3], a1, w3);
        FMA2(acc[2][0], a2, w0); FMA2(acc[2][1], a2, w1);
        FMA2(acc[2][2], a2, w2); FMA2(acc[2][3], a2, w3);
        FMA2(acc[3][0], a3, w0); FMA2(acc[3][1], a3, w1);
        FMA2(acc[3][2], a3, w2); FMA2(acc[3][3], a3, w3);
    }

    int head = tx >> 3;
    int cbase = head * 3 * HD + ((tx * 4) & 31);
    float4 a1v = *(const float4*)&a[cbase];
    float4 a2v = *(const float4*)&a[cbase + HD];

#pragma unroll
    for (int p = 0; p < 4; p++) {
#pragma unroll
        for (int half = 0; half < 2; half++) {
            union { ull u; float2 f; } c0, c1, c2, c3;
            c0.u = acc[p][0]; c1.u = acc[p][1]; c2.u = acc[p][2]; c3.u = acc[p][3];
            float f0 = half ? c0.f.y : c0.f.x;
            float f1 = half ? c1.f.y : c1.f.x;
            float f2 = half ? c2.f.y : c2.f.x;
            float f3 = half ? c3.f.y : c3.f.x;
            int gr = row0 + ty * 8 + p * 2 + half;
            if (gr < n)
                *(float4*)&g_h[(size_t)gr * ND + tx * 4] = make_float4(f0, f1, f2, f3);
            float d1 = f0 * a1v.x + f1 * a1v.y + f2 * a1v.z + f3 * a1v.w;
            float d2 = f0 * a2v.x + f1 * a2v.y + f2 * a2v.z + f3 * a2v.w;
#pragma unroll
            for (int o = 4; o >= 1; o >>= 1) {
                d1 += __shfl_down_sync(0xffffffffu, d1, o, 8);
                d2 += __shfl_down_sync(0xffffffffu, d2, o, 8);
            }
            if ((tx & 7) == 0 && gr < n) {
                g_s1[gr * NH + head] = d1;
                g_s2[gr * NH + head] = d2;
            }
        }
    }
}

// ---------------- launch 5: att scores + CSR scatter -------------------------
__global__ void kern_p1s(const float* __restrict__ edgef, const int* __restrict__ ei,
                         int n_edges) {
    __shared__ float vs[NH * ED];
    vs[threadIdx.x] = g_v[threadIdx.x];
    __syncthreads();

    int gid = blockIdx.x * 256 + threadIdx.x;
    int edge = gid >> 4;
    int l = threadIdx.x & 15;
    if (edge >= n_edges) return;

    float4 ef = *(const float4*)&edgef[(size_t)edge * ED + 4 * l];
    float p[NH];
#pragma unroll
    for (int h = 0; h < NH; h++) {
        const float* v = &vs[h * ED + 4 * l];
        p[h] = ef.x * v[0] + ef.y * v[1] + ef.z * v[2] + ef.w * v[3];
    }
#pragma unroll
    for (int o = 8; o >= 1; o >>= 1)
#pragma unroll
        for (int h = 0; h < NH; h++) p[h] += __shfl_down_sync(0xffffffffu, p[h], o, 16);

    if (l == 0) {
        int src = ei[edge];
        int tgt = ei[n_edges + edge];
        float4 s1 = *(const float4*)&g_s1[src * NH];
        float4 s2 = *(const float4*)&g_s2[tgt * NH];
        float a0 = s1.x + s2.x + p[0];
        float a1 = s1.y + s2.y + p[1];
        float a2 = s1.z + s2.z + p[2];
        float a3 = s1.w + s2.w + p[3];
        float4 o4;
        o4.x = a0 > 0.f ? a0 : 0.2f * a0;
        o4.y = a1 > 0.f ? a1 : 0.2f * a1;
        o4.z = a2 > 0.f ? a2 : 0.2f * a2;
        o4.w = a3 > 0.f ? a3 : 0.2f * a3;
        *(float4*)&g_att[(size_t)edge * NH] = o4;
        int pos = atomicAdd(&g_head[tgt], 1);
        g_csr[pos] = make_int2(edge, src);
    }
}

// ---------------- launch 6: fused softmax + aggregate (warp per node) --------
__global__ void kern_agg(float* __restrict__ out, int n_nodes, int n_edges) {
    int node = blockIdx.x * 8 + (threadIdx.x >> 5);
    int lane = threadIdx.x & 31;
    if (node >= n_nodes) return;
    int beg = g_off[node], end = g_off[node + 1];
    int deg = end - beg;
    int head = lane >> 3;

    // pass A: per-head max
    float4 mx = make_float4(-1e30f, -1e30f, -1e30f, -1e30f);
    for (int i = beg + lane; i < end; i += 32) {
        int e = g_csr[i].x;
        float4 v = *(const float4*)&g_att[(size_t)e * NH];
        mx.x = fmaxf(mx.x, v.x); mx.y = fmaxf(mx.y, v.y);
        mx.z = fmaxf(mx.z, v.z); mx.w = fmaxf(mx.w, v.w);
    }
#pragma unroll
    for (int o = 16; o; o >>= 1) {
        mx.x = fmaxf(mx.x, __shfl_xor_sync(0xffffffffu, mx.x, o));
        mx.y = fmaxf(mx.y, __shfl_xor_sync(0xffffffffu, mx.y, o));
        mx.z = fmaxf(mx.z, __shfl_xor_sync(0xffffffffu, mx.z, o));
        mx.w = fmaxf(mx.w, __shfl_xor_sync(0xffffffffu, mx.w, o));
    }
    float4 m = make_float4(fmaxf(mx.x, 0.f), fmaxf(mx.y, 0.f),
                           fmaxf(mx.z, 0.f), fmaxf(mx.w, 0.f));

    // pass B: sum of exp
    float4 s = make_float4(0.f, 0.f, 0.f, 0.f);
    for (int i = beg + lane; i < end; i += 32) {
        int e = g_csr[i].x;
        float4 v = *(const float4*)&g_att[(size_t)e * NH];
        s.x += __expf(v.x - m.x); s.y += __expf(v.y - m.y);
        s.z += __expf(v.z - m.z); s.w += __expf(v.w - m.w);
    }
#pragma unroll
    for (int o = 16; o; o >>= 1) {
        s.x += __shfl_xor_sync(0xffffffffu, s.x, o);
        s.y += __shfl_xor_sync(0xffffffffu, s.y, o);
        s.z += __shfl_xor_sync(0xffffffffu, s.z, o);
        s.w += __shfl_xor_sync(0xffffffffu, s.w, o);
    }
    float fE = (float)(n_edges - deg);
    float dx = s.x + fE * __expf(-m.x);
    float dy = s.y + fE * __expf(-m.y);
    float dz = s.z + fE * __expf(-m.z);
    float dw = s.w + fE * __expf(-m.w);
    float mh = (head == 0) ? m.x : (head == 1) ? m.y : (head == 2) ? m.z : m.w;
    float dh = (head == 0) ? dx : (head == 1) ? dy : (head == 2) ? dz : dw;
    float rd = 1.f / dh;

    // pass C: weighted gather-accumulate, unroll x4 for MLP
    float4 acc = make_float4(0.f, 0.f, 0.f, 0.f);
    for (int i = beg; i < end; i += 32) {
        int cnt = min(32, end - i);
        int2 es = make_int2(0, 0);
        if (lane < cnt) es = g_csr[i + lane];
        int j = 0;
        for (; j + 4 <= cnt; j += 4) {
            int e0 = __shfl_sync(0xffffffffu, es.x, j + 0);
            int s0 = __shfl_sync(0xffffffffu, es.y, j + 0);
            int e1 = __shfl_sync(0xffffffffu, es.x, j + 1);
            int s1 = __shfl_sync(0xffffffffu, es.y, j + 1);
            int e2 = __shfl_sync(0xffffffffu, es.x, j + 2);
            int s2 = __shfl_sync(0xffffffffu, es.y, j + 2);
            int e3 = __shfl_sync(0xffffffffu, es.x, j + 3);
            int s3 = __shfl_sync(0xffffffffu, es.y, j + 3);
            float v0 = __ldg(&g_att[(size_t)e0 * NH + head]);
            float v1 = __ldg(&g_att[(size_t)e1 * NH + head]);
            float v2 = __ldg(&g_att[(size_t)e2 * NH + head]);
            float v3 = __ldg(&g_att[(size_t)e3 * NH + head]);
            float4 h0 = *(const float4*)&g_h[(size_t)s0 * ND + 4 * lane];
            float4 h1 = *(const float4*)&g_h[(size_t)s1 * ND + 4 * lane];
            float4 h2 = *(const float4*)&g_h[(size_t)s2 * ND + 4 * lane];
            float4 h3 = *(const float4*)&g_h[(size_t)s3 * ND + 4 * lane];
            float w0 = __expf(v0 - mh) * rd;
            float w1 = __expf(v1 - mh) * rd;
            float w2 = __expf(v2 - mh) * rd;
            float w3 = __expf(v3 - mh) * rd;
            acc.x += w0 * h0.x + w1 * h1.x + w2 * h2.x + w3 * h3.x;
            acc.y += w0 * h0.y + w1 * h1.y + w2 * h2.y + w3 * h3.y;
            acc.z += w0 * h0.z + w1 * h1.z + w2 * h2.z + w3 * h3.z;
            acc.w += w0 * h0.w + w1 * h1.w + w2 * h2.w + w3 * h3.w;
        }
        for (; j < cnt; j++) {
            int ej = __shfl_sync(0xffffffffu, es.x, j);
            int sj = __shfl_sync(0xffffffffu, es.y, j);
            float w = __expf(__ldg(&g_att[(size_t)ej * NH + head]) - mh) * rd;
            float4 hv = *(const float4*)&g_h[(size_t)sj * ND + 4 * lane];
            acc.x += w * hv.x; acc.y += w * hv.y;
            acc.z += w * hv.z; acc.w += w * hv.w;
        }
    }
    *(float4*)&out[(size_t)node * ND + 4 * lane] = acc;
}

// ---------------- launch ------------------------------------------------------
extern "C" void kernel_launch(void* const* d_in, const int* in_sizes, int n_in,
                              void* d_out, int out_size) {
    const float* nodef = (const float*)d_in[0];
    const int* ei = (const int*)d_in[1];
    const float* edgef = (const float*)d_in[2];
    const float* W_node = (const float*)d_in[3];
    const float* W_edge = (const float*)d_in[4];
    const float* a = (const float*)d_in[5];
    float* out = (float*)d_out;

    int n_nodes = in_sizes[0] / ND;
    int n_edges = in_sizes[1] / 2;

    kern_init<<<(n_nodes + 1 + 255) / 256 + 1, 256>>>(W_edge, a, n_nodes);
    kern_hist<<<(n_edges + 255) / 256, 256>>>(ei, n_edges);
    kern_scan<<<1, 1024>>>(n_nodes, n_edges);

    const int gemm_smem = (128 * 132 + 128 * 66) * (int)sizeof(float);  // ~99KB
    cudaFuncSetAttribute(kern_gemm, cudaFuncAttributeMaxDynamicSharedMemorySize,
                         gemm_smem);
    kern_gemm<<<(n_nodes + 63) / 64, 256, gemm_smem>>>(nodef, W_node, a, n_nodes);

    kern_p1s<<<(n_edges + 15) / 16, 256>>>(edgef, ei, n_edges);
    kern_agg<<<(n_nodes + 7) / 8, 256>>>(out, n_nodes, n_edges);
}

// round 4
// speedup vs baseline: 1.3105x; 1.3105x over previous
#include <cuda_runtime.h>
#include <cstdint>

#define ND 128
#define ED 64
#define NH 4
#define HD 32
#define MAX_NODES 50000
#define MAX_EDGES 600000

typedef unsigned long long ull;

// ---------------- scratch (static device globals) ---------------------------
__device__ __align__(16) float g_h[MAX_NODES * ND];     // projected nodes
__device__ __align__(16) float g_s1[MAX_NODES * NH];    // h . a[:, 0:32]
__device__ __align__(16) float g_s2[MAX_NODES * NH];    // h . a[:, 32:64]
__device__ __align__(16) float g_att[MAX_EDGES * NH];   // leaky-relu scores
__device__ __align__(16) float g_v[NH * ED];            // folded edge attn vec
__device__ int g_cnt[MAX_NODES + 1];                    // degree histogram
__device__ int g_off[MAX_NODES + 1];                    // CSR row offsets
__device__ int g_head[MAX_NODES];                       // scatter cursors
__device__ __align__(8) int2 g_csr[MAX_EDGES];          // {edge id, src} per tgt
__device__ int g_part[64];                              // scan partials

#define FMA2(d, a, b) \
    asm("fma.rn.f32x2 %0, %1, %2, %0;" : "+l"(d) : "l"(a), "l"(b))
#define PACKDUP(d, f) \
    asm("mov.b64 %0, {%1, %1};" : "=l"(d) : "r"(__float_as_uint(f)))

// ---------------- launch 1: zero cnt/s1/s2 + fold W_edge into attn vector ---
__global__ void kern_init(const float* __restrict__ W_edge,
                          const float* __restrict__ a, int n, int Bc) {
    int b = blockIdx.x, nb = gridDim.x, t = threadIdx.x;
    if (b == nb - 1) {
        int h = t >> 6, k = t & 63;  // 256 == NH*ED
        float s = 0.f;
#pragma unroll
        for (int d = 0; d < HD; d++)
            s += W_edge[(h * HD + d) * ED + k] * __ldg(&a[h * 3 * HD + 2 * HD + d]);
        g_v[h * ED + k] = s;
    } else if (b < Bc) {
        int i = b * 256 + t;
        if (i <= n) g_cnt[i] = 0;
    } else {
        int i = (b - Bc) * 256 + t;
        if (i < n * NH) {
            g_s1[i] = 0.f;
            g_s2[i] = 0.f;
        }
    }
}

// ---------------- launch 2: degree histogram ---------------------------------
__global__ void kern_hist(const int* __restrict__ ei, int n_edges) {
    int e = blockIdx.x * blockDim.x + threadIdx.x;
    if (e < n_edges) atomicAdd(&g_cnt[ei[n_edges + e]], 1);
}

// ---------------- launch 3: scan partials (coalesced, multi-block) ----------
__global__ void kern_scan_part(int n) {  // 256 thr x 4 items
    __shared__ int wsum[8];
    int t = threadIdx.x;
    int base = blockIdx.x * 1024 + t * 4;
    int v0 = (base + 0 < n) ? g_cnt[base + 0] : 0;
    int v1 = (base + 1 < n) ? g_cnt[base + 1] : 0;
    int v2 = (base + 2 < n) ? g_cnt[base + 2] : 0;
    int v3 = (base + 3 < n) ? g_cnt[base + 3] : 0;
    int sum = v0 + v1 + v2 + v3;
    int lane = t & 31, w = t >> 5;
    int inc = sum;
#pragma unroll
    for (int o = 1; o < 32; o <<= 1) {
        int x = __shfl_up_sync(0xffffffffu, inc, o);
        if (lane >= o) inc += x;
    }
    if (lane == 31) wsum[w] = inc;
    __syncthreads();
    if (t == 0) {
        int acc = 0;
        for (int i = 0; i < 8; i++) { int x = wsum[i]; wsum[i] = acc; acc += x; }
    }
    __syncthreads();
    int excl = inc - sum + wsum[w];
    if (base + 0 < n) g_off[base + 0] = excl;
    if (base + 1 < n) g_off[base + 1] = excl + v0;
    if (base + 2 < n) g_off[base + 2] = excl + v0 + v1;
    if (base + 3 < n) g_off[base + 3] = excl + v0 + v1 + v2;
    if (t == 255) g_part[blockIdx.x] = excl + sum;
}

// ---------------- launch 4 (profiled): h = X @ W^T, broadcast-W f32x2 GEMM --
// 256 threads; tile 64 rows x 128 cols. warp w owns cols [16w,16w+16);
// lane l owns rows (2l, 2l+1). W pairs read as ulonglong2 broadcasts.
__global__ void __launch_bounds__(256, 2)
kern_gemm(const float* __restrict__ X, const float* __restrict__ W,
          const float* __restrict__ a, int n) {
    extern __shared__ float sm[];
    float* Ws = sm;               // [128 k][132 cols] k-major
    float* At = sm + 128 * 132;  // [128 k][66 rows]  k-major
    int t = threadIdx.x;

    for (int i = t; i < ND * ND; i += 256) {
        int j = i >> 7, k = i & 127;
        Ws[k * 132 + j] = W[i];
    }
    int row0 = blockIdx.x * 64;
    for (int i = t; i < 64 * ND; i += 256) {
        int r = i >> 7, k = i & 127;
        int gr = row0 + r;
        At[k * 66 + r] = (gr < n) ? X[(size_t)gr * ND + k] : 0.f;
    }
    __syncthreads();

    int w = t >> 5, lane = t & 31;
    ull acc[2][8];
#pragma unroll
    for (int r = 0; r < 2; r++)
#pragma unroll
        for (int c = 0; c < 8; c++) acc[r][c] = 0ULL;

    const float* arp = At + 2 * lane;
    const float* wrp = Ws + (w << 4);

#pragma unroll 4
    for (int k = 0; k < ND; k++) {
        float r0 = arp[k * 66];
        float r1 = arp[k * 66 + 1];
        ull d0, d1;
        PACKDUP(d0, r0);
        PACKDUP(d1, r1);
        ulonglong2 p0 = *(const ulonglong2*)(wrp + k * 132 + 0);
        ulonglong2 p1 = *(const ulonglong2*)(wrp + k * 132 + 4);
        ulonglong2 p2 = *(const ulonglong2*)(wrp + k * 132 + 8);
        ulonglong2 p3 = *(const ulonglong2*)(wrp + k * 132 + 12);
        FMA2(acc[0][0], p0.x, d0); FMA2(acc[0][1], p0.y, d0);
        FMA2(acc[0][2], p1.x, d0); FMA2(acc[0][3], p1.y, d0);
        FMA2(acc[0][4], p2.x, d0); FMA2(acc[0][5], p2.y, d0);
        FMA2(acc[0][6], p3.x, d0); FMA2(acc[0][7], p3.y, d0);
        FMA2(acc[1][0], p0.x, d1); FMA2(acc[1][1], p0.y, d1);
        FMA2(acc[1][2], p1.x, d1); FMA2(acc[1][3], p1.y, d1);
        FMA2(acc[1][4], p2.x, d1); FMA2(acc[1][5], p2.y, d1);
        FMA2(acc[1][6], p3.x, d1); FMA2(acc[1][7], p3.y, d1);
    }

    // epilogue: store h rows + partial s1/s2 dots (atomic reduce across warps)
    int hd = w >> 1;
    int coff = (w & 1) << 4;  // offset within the 32-wide head
    float a1v[16], a2v[16];
#pragma unroll
    for (int c = 0; c < 4; c++) {
        *(float4*)&a1v[4 * c] = *(const float4*)&a[hd * 3 * HD + coff + 4 * c];
        *(float4*)&a2v[4 * c] = *(const float4*)&a[hd * 3 * HD + HD + coff + 4 * c];
    }
#pragma unroll
    for (int r = 0; r < 2; r++) {
        int gr = row0 + 2 * lane + r;
        if (gr >= n) continue;
        float f[16];
#pragma unroll
        for (int cp = 0; cp < 8; cp++) {
            union { ull u; float2 v; } cu;
            cu.u = acc[r][cp];
            f[2 * cp] = cu.v.x;
            f[2 * cp + 1] = cu.v.y;
        }
#pragma unroll
        for (int c = 0; c < 4; c++)
            *(float4*)&g_h[(size_t)gr * ND + (w << 4) + 4 * c] =
                make_float4(f[4 * c], f[4 * c + 1], f[4 * c + 2], f[4 * c + 3]);
        float d1 = 0.f, d2 = 0.f;
#pragma unroll
        for (int j = 0; j < 16; j++) {
            d1 += f[j] * a1v[j];
            d2 += f[j] * a2v[j];
        }
        atomicAdd(&g_s1[gr * NH + hd], d1);
        atomicAdd(&g_s2[gr * NH + hd], d2);
    }
}

// ---------------- launch 5/6: scan top + add ---------------------------------
__global__ void kern_scan_top(int nb) {  // 1 block, 64 threads
    __shared__ int ws[2];
    int t = threadIdx.x;
    int v = (t < nb) ? g_part[t] : 0;
    int lane = t & 31, w = t >> 5;
    int inc = v;
#pragma unroll
    for (int o = 1; o < 32; o <<= 1) {
        int x = __shfl_up_sync(0xffffffffu, inc, o);
        if (lane >= o) inc += x;
    }
    if (lane == 31) ws[w] = inc;
    __syncthreads();
    int add = (w == 1) ? ws[0] : 0;
    if (t < nb) g_part[t] = inc - v + add;
}

__global__ void kern_scan_add(int n, int n_edges) {
    int i = blockIdx.x * blockDim.x + threadIdx.x;
    if (i < n) {
        int o = g_off[i] + g_part[i >> 10];
        g_off[i] = o;
        g_head[i] = o;
    }
    if (i == 0) g_off[n] = n_edges;
}

// ---------------- launch 7: att scores + CSR scatter -------------------------
__global__ void kern_p1s(const float* __restrict__ edgef, const int* __restrict__ ei,
                         int n_edges) {
    __shared__ float vs[NH * ED];
    vs[threadIdx.x] = g_v[threadIdx.x];
    __syncthreads();

    int gid = blockIdx.x * 256 + threadIdx.x;
    int edge = gid >> 4;
    int l = threadIdx.x & 15;
    if (edge >= n_edges) return;

    float4 ef = *(const float4*)&edgef[(size_t)edge * ED + 4 * l];
    float p[NH];
#pragma unroll
    for (int h = 0; h < NH; h++) {
        const float* v = &vs[h * ED + 4 * l];
        p[h] = ef.x * v[0] + ef.y * v[1] + ef.z * v[2] + ef.w * v[3];
    }
#pragma unroll
    for (int o = 8; o >= 1; o >>= 1)
#pragma unroll
        for (int h = 0; h < NH; h++) p[h] += __shfl_down_sync(0xffffffffu, p[h], o, 16);

    if (l == 0) {
        int src = ei[edge];
        int tgt = ei[n_edges + edge];
        float4 s1 = *(const float4*)&g_s1[src * NH];
        float4 s2 = *(const float4*)&g_s2[tgt * NH];
        float a0 = s1.x + s2.x + p[0];
        float a1 = s1.y + s2.y + p[1];
        float a2 = s1.z + s2.z + p[2];
        float a3 = s1.w + s2.w + p[3];
        float4 o4;
        o4.x = a0 > 0.f ? a0 : 0.2f * a0;
        o4.y = a1 > 0.f ? a1 : 0.2f * a1;
        o4.z = a2 > 0.f ? a2 : 0.2f * a2;
        o4.w = a3 > 0.f ? a3 : 0.2f * a3;
        *(float4*)&g_att[(size_t)edge * NH] = o4;
        int pos = atomicAdd(&g_head[tgt], 1);
        g_csr[pos] = make_int2(edge, src);
    }
}

// ---------------- launch 8: fused softmax + aggregate (warp per node) --------
__global__ void kern_agg(float* __restrict__ out, int n_nodes, int n_edges) {
    int node = blockIdx.x * 8 + (threadIdx.x >> 5);
    int lane = threadIdx.x & 31;
    if (node >= n_nodes) return;
    int beg = g_off[node], end = g_off[node + 1];
    int deg = end - beg;
    int head = lane >> 3;

    // pass A: per-head max
    float4 mx = make_float4(-1e30f, -1e30f, -1e30f, -1e30f);
    for (int i = beg + lane; i < end; i += 32) {
        int e = g_csr[i].x;
        float4 v = *(const float4*)&g_att[(size_t)e * NH];
        mx.x = fmaxf(mx.x, v.x); mx.y = fmaxf(mx.y, v.y);
        mx.z = fmaxf(mx.z, v.z); mx.w = fmaxf(mx.w, v.w);
    }
#pragma unroll
    for (int o = 16; o; o >>= 1) {
        mx.x = fmaxf(mx.x, __shfl_xor_sync(0xffffffffu, mx.x, o));
        mx.y = fmaxf(mx.y, __shfl_xor_sync(0xffffffffu, mx.y, o));
        mx.z = fmaxf(mx.z, __shfl_xor_sync(0xffffffffu, mx.z, o));
        mx.w = fmaxf(mx.w, __shfl_xor_sync(0xffffffffu, mx.w, o));
    }
    float4 m = make_float4(fmaxf(mx.x, 0.f), fmaxf(mx.y, 0.f),
                           fmaxf(mx.z, 0.f), fmaxf(mx.w, 0.f));

    // pass B: sum of exp
    float4 s = make_float4(0.f, 0.f, 0.f, 0.f);
    for (int i = beg + lane; i < end; i += 32) {
        int e = g_csr[i].x;
        float4 v = *(const float4*)&g_att[(size_t)e * NH];
        s.x += __expf(v.x - m.x); s.y += __expf(v.y - m.y);
        s.z += __expf(v.z - m.z); s.w += __expf(v.w - m.w);
    }
#pragma unroll
    for (int o = 16; o; o >>= 1) {
        s.x += __shfl_xor_sync(0xffffffffu, s.x, o);
        s.y += __shfl_xor_sync(0xffffffffu, s.y, o);
        s.z += __shfl_xor_sync(0xffffffffu, s.z, o);
        s.w += __shfl_xor_sync(0xffffffffu, s.w, o);
    }
    float fE = (float)(n_edges - deg);
    float dx = s.x + fE * __expf(-m.x);
    float dy = s.y + fE * __expf(-m.y);
    float dz = s.z + fE * __expf(-m.z);
    float dw = s.w + fE * __expf(-m.w);
    float mh = (head == 0) ? m.x : (head == 1) ? m.y : (head == 2) ? m.z : m.w;
    float dh = (head == 0) ? dx : (head == 1) ? dy : (head == 2) ? dz : dw;
    float rd = 1.f / dh;

    // pass C: weighted gather-accumulate, unroll x4 for MLP
    float4 acc = make_float4(0.f, 0.f, 0.f, 0.f);
    for (int i = beg; i < end; i += 32) {
        int cnt = min(32, end - i);
        int2 es = make_int2(0, 0);
        if (lane < cnt) es = g_csr[i + lane];
        int j = 0;
        for (; j + 4 <= cnt; j += 4) {
            int e0 = __shfl_sync(0xffffffffu, es.x, j + 0);
            int s0 = __shfl_sync(0xffffffffu, es.y, j + 0);
            int e1 = __shfl_sync(0xffffffffu, es.x, j + 1);
            int s1 = __shfl_sync(0xffffffffu, es.y, j + 1);
            int e2 = __shfl_sync(0xffffffffu, es.x, j + 2);
            int s2 = __shfl_sync(0xffffffffu, es.y, j + 2);
            int e3 = __shfl_sync(0xffffffffu, es.x, j + 3);
            int s3 = __shfl_sync(0xffffffffu, es.y, j + 3);
            float v0 = __ldg(&g_att[(size_t)e0 * NH + head]);
            float v1 = __ldg(&g_att[(size_t)e1 * NH + head]);
            float v2 = __ldg(&g_att[(size_t)e2 * NH + head]);
            float v3 = __ldg(&g_att[(size_t)e3 * NH + head]);
            float4 h0 = *(const float4*)&g_h[(size_t)s0 * ND + 4 * lane];
            float4 h1 = *(const float4*)&g_h[(size_t)s1 * ND + 4 * lane];
            float4 h2 = *(const float4*)&g_h[(size_t)s2 * ND + 4 * lane];
            float4 h3 = *(const float4*)&g_h[(size_t)s3 * ND + 4 * lane];
            float w0 = __expf(v0 - mh) * rd;
            float w1 = __expf(v1 - mh) * rd;
            float w2 = __expf(v2 - mh) * rd;
            float w3 = __expf(v3 - mh) * rd;
            acc.x += w0 * h0.x + w1 * h1.x + w2 * h2.x + w3 * h3.x;
            acc.y += w0 * h0.y + w1 * h1.y + w2 * h2.y + w3 * h3.y;
            acc.z += w0 * h0.z + w1 * h1.z + w2 * h2.z + w3 * h3.z;
            acc.w += w0 * h0.w + w1 * h1.w + w2 * h2.w + w3 * h3.w;
        }
        for (; j < cnt; j++) {
            int ej = __shfl_sync(0xffffffffu, es.x, j);
            int sj = __shfl_sync(0xffffffffu, es.y, j);
            float w = __expf(__ldg(&g_att[(size_t)ej * NH + head]) - mh) * rd;
            float4 hv = *(const float4*)&g_h[(size_t)sj * ND + 4 * lane];
            acc.x += w * hv.x; acc.y += w * hv.y;
            acc.z += w * hv.z; acc.w += w * hv.w;
        }
    }
    *(float4*)&out[(size_t)node * ND + 4 * lane] = acc;
}

// ---------------- launch ------------------------------------------------------
extern "C" void kernel_launch(void* const* d_in, const int* in_sizes, int n_in,
                              void* d_out, int out_size) {
    const float* nodef = (const float*)d_in[0];
    const int* ei = (const int*)d_in[1];
    const float* edgef = (const float*)d_in[2];
    const float* W_node = (const float*)d_in[3];
    const float* W_edge = (const float*)d_in[4];
    const float* a = (const float*)d_in[5];
    float* out = (float*)d_out;

    int n_nodes = in_sizes[0] / ND;
    int n_edges = in_sizes[1] / 2;
    int nb = (n_nodes + 1023) >> 10;
    int Bc = (n_nodes + 1 + 255) / 256;
    int Bs = (n_nodes * NH + 255) / 256;

    kern_init<<<Bc + Bs + 1, 256>>>(W_edge, a, n_nodes, Bc);        // 1
    kern_hist<<<(n_edges + 255) / 256, 256>>>(ei, n_edges);         // 2
    kern_scan_part<<<nb, 256>>>(n_nodes);                           // 3

    const int gemm_smem = (128 * 132 + 128 * 66) * (int)sizeof(float);  // ~99KB
    cudaFuncSetAttribute(kern_gemm, cudaFuncAttributeMaxDynamicSharedMemorySize,
                         gemm_smem);
    kern_gemm<<<(n_nodes + 63) / 64, 256, gemm_smem>>>(nodef, W_node, a, n_nodes);  // 4

    kern_scan_top<<<1, 64>>>(nb);                                   // 5
    kern_scan_add<<<(n_nodes + 255) / 256, 256>>>(n_nodes, n_edges);  // 6
    kern_p1s<<<(n_edges + 15) / 16, 256>>>(edgef, ei, n_edges);     // 7
    kern_agg<<<(n_nodes + 7) / 8, 256>>>(out, n_nodes, n_edges);    // 8
}

// round 5
// speedup vs baseline: 1.3567x; 1.0353x over previous
#include <cuda_runtime.h>
#include <cstdint>

#define ND 128
#define ED 64
#define NH 4
#define HD 32
#define MAX_NODES 50000
#define MAX_EDGES 600000

typedef unsigned long long ull;

// ---------------- scratch (static device globals) ---------------------------
__device__ __align__(16) float g_h[MAX_NODES * ND];     // projected nodes
__device__ __align__(16) float g_s1[MAX_NODES * NH];    // h . a[:, 0:32]
__device__ __align__(16) float g_s2[MAX_NODES * NH];    // h . a[:, 32:64]
__device__ __align__(16) float g_att[MAX_EDGES * NH];   // leaky-relu scores
__device__ __align__(16) float g_v[NH * ED];            // folded edge attn vec
__device__ int g_cnt[MAX_NODES + 1];                    // degree histogram
__device__ int g_off[MAX_NODES + 1];                    // CSR row offsets
__device__ int g_head[MAX_NODES];                       // scatter cursors
__device__ __align__(8) int2 g_csr[MAX_EDGES];          // {edge id, src} per tgt
__device__ int g_part[64];                              // scan partials

#define FMA2(d, a, b) \
    asm("fma.rn.f32x2 %0, %1, %2, %0;" : "+l"(d) : "l"(a), "l"(b))
#define PACKDUP(d, f) \
    asm("mov.b64 %0, {%1, %1};" : "=l"(d) : "r"(__float_as_uint(f)))

// ---------------- launch 1: zero cnt + fold W_edge into attn vector ---------
__global__ void kern_init(const float* __restrict__ W_edge,
                          const float* __restrict__ a, int n) {
    int b = blockIdx.x, nb = gridDim.x, t = threadIdx.x;
    if (b == nb - 1) {
        int h = t >> 6, k = t & 63;  // 256 == NH*ED
        float s = 0.f;
#pragma unroll
        for (int d = 0; d < HD; d++)
            s += W_edge[(h * HD + d) * ED + k] * __ldg(&a[h * 3 * HD + 2 * HD + d]);
        g_v[h * ED + k] = s;
    } else {
        int i = b * 256 + t;
        if (i <= n) g_cnt[i] = 0;
    }
}

// ---------------- launch 2: degree histogram ---------------------------------
__global__ void kern_hist(const int* __restrict__ ei, int n_edges) {
    int e = blockIdx.x * blockDim.x + threadIdx.x;
    if (e < n_edges) atomicAdd(&g_cnt[ei[n_edges + e]], 1);
}

// ---------------- launch 3: scan partials ------------------------------------
__global__ void kern_scan_part(int n) {  // 256 thr x 4 items
    __shared__ int wsum[8];
    int t = threadIdx.x;
    int base = blockIdx.x * 1024 + t * 4;
    int v0 = (base + 0 < n) ? g_cnt[base + 0] : 0;
    int v1 = (base + 1 < n) ? g_cnt[base + 1] : 0;
    int v2 = (base + 2 < n) ? g_cnt[base + 2] : 0;
    int v3 = (base + 3 < n) ? g_cnt[base + 3] : 0;
    int sum = v0 + v1 + v2 + v3;
    int lane = t & 31, w = t >> 5;
    int inc = sum;
#pragma unroll
    for (int o = 1; o < 32; o <<= 1) {
        int x = __shfl_up_sync(0xffffffffu, inc, o);
        if (lane >= o) inc += x;
    }
    if (lane == 31) wsum[w] = inc;
    __syncthreads();
    if (t == 0) {
        int acc = 0;
        for (int i = 0; i < 8; i++) { int x = wsum[i]; wsum[i] = acc; acc += x; }
    }
    __syncthreads();
    int excl = inc - sum + wsum[w];
    if (base + 0 < n) g_off[base + 0] = excl;
    if (base + 1 < n) g_off[base + 1] = excl + v0;
    if (base + 2 < n) g_off[base + 2] = excl + v0 + v1;
    if (base + 3 < n) g_off[base + 3] = excl + v0 + v1 + v2;
    if (t == 255) g_part[blockIdx.x] = excl + sum;
}

// ---------------- launch 4 (profiled): h = X @ W^T f32x2 GEMM + s1/s2 -------
// r2 skeleton: tile 64 rows x 128 cols; thread (tx,ty): cols 4tx..4tx+3,
// rows 8ty..8ty+7 as 4 f32x2 pairs. A pairs loaded as 2x LDS.128 broadcast.
__global__ void __launch_bounds__(256, 2)
kern_gemm(const float* __restrict__ X, const float* __restrict__ W,
          const float* __restrict__ a, int n) {
    extern __shared__ float sm[];
    float* Ws = sm;               // [128 k][132 cols]
    float* At = sm + 128 * 132;  // [128 k][68 rows] (ull stride 34)
    int t = threadIdx.x;

    for (int i = t; i < ND * ND; i += 256) {
        int j = i >> 7, k = i & 127;
        Ws[k * 132 + j] = W[i];
    }
    int row0 = blockIdx.x * 64;
    for (int i = t; i < 64 * ND; i += 256) {
        int r = i >> 7, k = i & 127;
        int gr = row0 + r;
        At[k * 68 + r] = (gr < n) ? X[(size_t)gr * ND + k] : 0.f;
    }
    __syncthreads();

    int tx = t & 31, ty = t >> 5;
    ull acc[4][4];
#pragma unroll
    for (int p = 0; p < 4; p++)
#pragma unroll
        for (int c = 0; c < 4; c++) acc[p][c] = 0ULL;

    const ulonglong2* ab = (const ulonglong2*)At + ty * 2;  // + k*17 per step
    const float* wb = &Ws[tx * 4];

#pragma unroll 4
    for (int k = 0; k < ND; k++) {
        float4 wv = *(const float4*)(wb + k * 132);
        ull w0, w1, w2, w3;
        PACKDUP(w0, wv.x); PACKDUP(w1, wv.y); PACKDUP(w2, wv.z); PACKDUP(w3, wv.w);
        ulonglong2 A0 = ab[k * 17];      // row pairs 0,1
        ulonglong2 A1 = ab[k * 17 + 1];  // row pairs 2,3
        FMA2(acc[0][0], A0.x, w0); FMA2(acc[0][1], A0.x, w1);
        FMA2(acc[0][2], A0.x, w2); FMA2(acc[0][3], A0.x, w3);
        FMA2(acc[1][0], A0.y, w0); FMA2(acc[1][1], A0.y, w1);
        FMA2(acc[1][2], A0.y, w2); FMA2(acc[1][3], A0.y, w3);
        FMA2(acc[2][0], A1.x, w0); FMA2(acc[2][1], A1.x, w1);
        FMA2(acc[2][2], A1.x, w2); FMA2(acc[2][3], A1.x, w3);
        FMA2(acc[3][0], A1.y, w0); FMA2(acc[3][1], A1.y, w1);
        FMA2(acc[3][2], A1.y, w2); FMA2(acc[3][3], A1.y, w3);
    }

    // epilogue: coalesced h stores + per-head s1/s2 dots (8-lane shfl groups)
    int head = tx >> 3;
    int cbase = head * 3 * HD + ((tx * 4) & 31);
    float4 a1v = *(const float4*)&a[cbase];
    float4 a2v = *(const float4*)&a[cbase + HD];

#pragma unroll
    for (int p = 0; p < 4; p++) {
#pragma unroll
        for (int half = 0; half < 2; half++) {
            union { ull u; float2 f; } c0, c1, c2, c3;
            c0.u = acc[p][0]; c1.u = acc[p][1]; c2.u = acc[p][2]; c3.u = acc[p][3];
            float f0 = half ? c0.f.y : c0.f.x;
            float f1 = half ? c1.f.y : c1.f.x;
            float f2 = half ? c2.f.y : c2.f.x;
            float f3 = half ? c3.f.y : c3.f.x;
            int gr = row0 + ty * 8 + p * 2 + half;
            if (gr < n)
                *(float4*)&g_h[(size_t)gr * ND + tx * 4] = make_float4(f0, f1, f2, f3);
            float d1 = f0 * a1v.x + f1 * a1v.y + f2 * a1v.z + f3 * a1v.w;
            float d2 = f0 * a2v.x + f1 * a2v.y + f2 * a2v.z + f3 * a2v.w;
#pragma unroll
            for (int o = 4; o >= 1; o >>= 1) {
                d1 += __shfl_down_sync(0xffffffffu, d1, o, 8);
                d2 += __shfl_down_sync(0xffffffffu, d2, o, 8);
            }
            if ((tx & 7) == 0 && gr < n) {
                g_s1[gr * NH + head] = d1;
                g_s2[gr * NH + head] = d2;
            }
        }
    }
}

// ---------------- launch 5/6: scan top + add ---------------------------------
__global__ void kern_scan_top(int nb) {  // 1 block, 64 threads
    __shared__ int ws[2];
    int t = threadIdx.x;
    int v = (t < nb) ? g_part[t] : 0;
    int lane = t & 31, w = t >> 5;
    int inc = v;
#pragma unroll
    for (int o = 1; o < 32; o <<= 1) {
        int x = __shfl_up_sync(0xffffffffu, inc, o);
        if (lane >= o) inc += x;
    }
    if (lane == 31) ws[w] = inc;
    __syncthreads();
    int add = (w == 1) ? ws[0] : 0;
    if (t < nb) g_part[t] = inc - v + add;
}

__global__ void kern_scan_add(int n, int n_edges) {
    int i = blockIdx.x * blockDim.x + threadIdx.x;
    if (i < n) {
        int o = g_off[i] + g_part[i >> 10];
        g_off[i] = o;
        g_head[i] = o;
    }
    if (i == 0) g_off[n] = n_edges;
}

// ---------------- launch 7: att scores + CSR scatter -------------------------
__global__ void kern_p1s(const float* __restrict__ edgef, const int* __restrict__ ei,
                         int n_edges) {
    __shared__ float vs[NH * ED];
    vs[threadIdx.x] = g_v[threadIdx.x];
    __syncthreads();

    int gid = blockIdx.x * 256 + threadIdx.x;
    int edge = gid >> 4;
    int l = threadIdx.x & 15;
    if (edge >= n_edges) return;

    float4 ef = *(const float4*)&edgef[(size_t)edge * ED + 4 * l];
    float p[NH];
#pragma unroll
    for (int h = 0; h < NH; h++) {
        const float* v = &vs[h * ED + 4 * l];
        p[h] = ef.x * v[0] + ef.y * v[1] + ef.z * v[2] + ef.w * v[3];
    }
#pragma unroll
    for (int o = 8; o >= 1; o >>= 1)
#pragma unroll
        for (int h = 0; h < NH; h++) p[h] += __shfl_down_sync(0xffffffffu, p[h], o, 16);

    if (l == 0) {
        int src = ei[edge];
        int tgt = ei[n_edges + edge];
        float4 s1 = *(const float4*)&g_s1[src * NH];
        float4 s2 = *(const float4*)&g_s2[tgt * NH];
        float a0 = s1.x + s2.x + p[0];
        float a1 = s1.y + s2.y + p[1];
        float a2 = s1.z + s2.z + p[2];
        float a3 = s1.w + s2.w + p[3];
        float4 o4;
        o4.x = a0 > 0.f ? a0 : 0.2f * a0;
        o4.y = a1 > 0.f ? a1 : 0.2f * a1;
        o4.z = a2 > 0.f ? a2 : 0.2f * a2;
        o4.w = a3 > 0.f ? a3 : 0.2f * a3;
        *(float4*)&g_att[(size_t)edge * NH] = o4;
        int pos = atomicAdd(&g_head[tgt], 1);
        g_csr[pos] = make_int2(edge, src);
    }
}

// ---------------- launch 8: online softmax + aggregate (warp per node) -------
__global__ void kern_agg(float* __restrict__ out, int n_nodes, int n_edges) {
    int node = blockIdx.x * 8 + (threadIdx.x >> 5);
    int lane = threadIdx.x & 31;
    if (node >= n_nodes) return;
    int beg = g_off[node], end = g_off[node + 1];
    int deg = end - beg;
    int head = lane >> 3;

    // fused pass A+B: online (m, s) per lane, m init 0 (dense-softmax floor)
    float4 m = make_float4(0.f, 0.f, 0.f, 0.f);
    float4 s = make_float4(0.f, 0.f, 0.f, 0.f);
    for (int i = beg + lane; i < end; i += 32) {
        int e = g_csr[i].x;
        float4 v = *(const float4*)&g_att[(size_t)e * NH];
        float nm;
        nm = fmaxf(m.x, v.x); s.x = s.x * __expf(m.x - nm) + __expf(v.x - nm); m.x = nm;
        nm = fmaxf(m.y, v.y); s.y = s.y * __expf(m.y - nm) + __expf(v.y - nm); m.y = nm;
        nm = fmaxf(m.z, v.z); s.z = s.z * __expf(m.z - nm) + __expf(v.z - nm); m.z = nm;
        nm = fmaxf(m.w, v.w); s.w = s.w * __expf(m.w - nm) + __expf(v.w - nm); m.w = nm;
    }
    // reduce max across lanes
    float4 M = m;
#pragma unroll
    for (int o = 16; o; o >>= 1) {
        M.x = fmaxf(M.x, __shfl_xor_sync(0xffffffffu, M.x, o));
        M.y = fmaxf(M.y, __shfl_xor_sync(0xffffffffu, M.y, o));
        M.z = fmaxf(M.z, __shfl_xor_sync(0xffffffffu, M.z, o));
        M.w = fmaxf(M.w, __shfl_xor_sync(0xffffffffu, M.w, o));
    }
    // rescale lane sums to global max, then sum-reduce
    s.x *= __expf(m.x - M.x);
    s.y *= __expf(m.y - M.y);
    s.z *= __expf(m.z - M.z);
    s.w *= __expf(m.w - M.w);
#pragma unroll
    for (int o = 16; o; o >>= 1) {
        s.x += __shfl_xor_sync(0xffffffffu, s.x, o);
        s.y += __shfl_xor_sync(0xffffffffu, s.y, o);
        s.z += __shfl_xor_sync(0xffffffffu, s.z, o);
        s.w += __shfl_xor_sync(0xffffffffu, s.w, o);
    }
    float fE = (float)(n_edges - deg);
    float dx = s.x + fE * __expf(-M.x);
    float dy = s.y + fE * __expf(-M.y);
    float dz = s.z + fE * __expf(-M.z);
    float dw = s.w + fE * __expf(-M.w);
    float mh = (head == 0) ? M.x : (head == 1) ? M.y : (head == 2) ? M.z : M.w;
    float dh = (head == 0) ? dx : (head == 1) ? dy : (head == 2) ? dz : dw;
    float rd = 1.f / dh;

    // pass C: weighted gather-accumulate, unroll x4 for MLP
    float4 acc = make_float4(0.f, 0.f, 0.f, 0.f);
    for (int i = beg; i < end; i += 32) {
        int cnt = min(32, end - i);
        int2 es = make_int2(0, 0);
        if (lane < cnt) es = g_csr[i + lane];
        int j = 0;
        for (; j + 4 <= cnt; j += 4) {
            int e0 = __shfl_sync(0xffffffffu, es.x, j + 0);
            int s0 = __shfl_sync(0xffffffffu, es.y, j + 0);
            int e1 = __shfl_sync(0xffffffffu, es.x, j + 1);
            int s1 = __shfl_sync(0xffffffffu, es.y, j + 1);
            int e2 = __shfl_sync(0xffffffffu, es.x, j + 2);
            int s2 = __shfl_sync(0xffffffffu, es.y, j + 2);
            int e3 = __shfl_sync(0xffffffffu, es.x, j + 3);
            int s3 = __shfl_sync(0xffffffffu, es.y, j + 3);
            float v0 = __ldg(&g_att[(size_t)e0 * NH + head]);
            float v1 = __ldg(&g_att[(size_t)e1 * NH + head]);
            float v2 = __ldg(&g_att[(size_t)e2 * NH + head]);
            float v3 = __ldg(&g_att[(size_t)e3 * NH + head]);
            float4 h0 = *(const float4*)&g_h[(size_t)s0 * ND + 4 * lane];
            float4 h1 = *(const float4*)&g_h[(size_t)s1 * ND + 4 * lane];
            float4 h2 = *(const float4*)&g_h[(size_t)s2 * ND + 4 * lane];
            float4 h3 = *(const float4*)&g_h[(size_t)s3 * ND + 4 * lane];
            float w0 = __expf(v0 - mh) * rd;
            float w1 = __expf(v1 - mh) * rd;
            float w2 = __expf(v2 - mh) * rd;
            float w3 = __expf(v3 - mh) * rd;
            acc.x += w0 * h0.x + w1 * h1.x + w2 * h2.x + w3 * h3.x;
            acc.y += w0 * h0.y + w1 * h1.y + w2 * h2.y + w3 * h3.y;
            acc.z += w0 * h0.z + w1 * h1.z + w2 * h2.z + w3 * h3.z;
            acc.w += w0 * h0.w + w1 * h1.w + w2 * h2.w + w3 * h3.w;
        }
        for (; j < cnt; j++) {
            int ej = __shfl_sync(0xffffffffu, es.x, j);
            int sj = __shfl_sync(0xffffffffu, es.y, j);
            float w = __expf(__ldg(&g_att[(size_t)ej * NH + head]) - mh) * rd;
            float4 hv = *(const float4*)&g_h[(size_t)sj * ND + 4 * lane];
            acc.x += w * hv.x; acc.y += w * hv.y;
            acc.z += w * hv.z; acc.w += w * hv.w;
        }
    }
    *(float4*)&out[(size_t)node * ND + 4 * lane] = acc;
}

// ---------------- launch ------------------------------------------------------
extern "C" void kernel_launch(void* const* d_in, const int* in_sizes, int n_in,
                              void* d_out, int out_size) {
    const float* nodef = (const float*)d_in[0];
    const int* ei = (const int*)d_in[1];
    const float* edgef = (const float*)d_in[2];
    const float* W_node = (const float*)d_in[3];
    const float* W_edge = (const float*)d_in[4];
    const float* a = (const float*)d_in[5];
    float* out = (float*)d_out;

    int n_nodes = in_sizes[0] / ND;
    int n_edges = in_sizes[1] / 2;
    int nb = (n_nodes + 1023) >> 10;
    int Bc = (n_nodes + 1 + 255) / 256;

    kern_init<<<Bc + 1, 256>>>(W_edge, a, n_nodes);                 // 1
    kern_hist<<<(n_edges + 255) / 256, 256>>>(ei, n_edges);         // 2
    kern_scan_part<<<nb, 256>>>(n_nodes);                           // 3

    const int gemm_smem = (128 * 132 + 128 * 68) * (int)sizeof(float);  // 100KB
    cudaFuncSetAttribute(kern_gemm, cudaFuncAttributeMaxDynamicSharedMemorySize,
                         gemm_smem);
    kern_gemm<<<(n_nodes + 63) / 64, 256, gemm_smem>>>(nodef, W_node, a, n_nodes);  // 4

    kern_scan_top<<<1, 64>>>(nb);                                   // 5
    kern_scan_add<<<(n_nodes + 255) / 256, 256>>>(n_nodes, n_edges);  // 6
    kern_p1s<<<(n_edges + 15) / 16, 256>>>(edgef, ei, n_edges);     // 7
    kern_agg<<<(n_nodes + 7) / 8, 256>>>(out, n_nodes, n_edges);    // 8
}

// round 7
// speedup vs baseline: 1.3664x; 1.0071x over previous
#include <cuda_runtime.h>
#include <cstdint>

#define ND 128
#define ED 64
#define NH 4
#define HD 32
#define MAX_NODES 50000
#define MAX_EDGES 600000

typedef unsigned long long ull;

// ---------------- scratch (static device globals) ---------------------------
__device__ __align__(16) float g_h[MAX_NODES * ND];     // projected nodes
__device__ __align__(16) float g_s1[MAX_NODES * NH];    // h . a[:, 0:32]
__device__ __align__(16) float g_s2[MAX_NODES * NH];    // h . a[:, 32:64]
__device__ __align__(16) float g_att[MAX_EDGES * NH];   // leaky-relu scores
__device__ __align__(16) float g_v[NH * ED];            // folded edge attn vec
__device__ int g_cnt[MAX_NODES + 1];                    // degree histogram
__device__ int g_off[MAX_NODES + 1];                    // CSR row offsets
__device__ int g_head[MAX_NODES];                       // scatter cursors
__device__ __align__(8) int2 g_csr[MAX_EDGES];          // {edge id, src} per tgt
__device__ int g_part[64];                              // scan partials

#define FMA2(d, a, b) \
    asm("fma.rn.f32x2 %0, %1, %2, %0;" : "+l"(d) : "l"(a), "l"(b))
#define PACKDUP(d, f) \
    asm("mov.b64 %0, {%1, %1};" : "=l"(d) : "r"(__float_as_uint(f)))

// ---------------- launch 1: zero cnt + fold W_edge into attn vector ---------
__global__ void kern_init(const float* __restrict__ W_edge,
                          const float* __restrict__ a, int n) {
    int b = blockIdx.x, nb = gridDim.x, t = threadIdx.x;
    if (b == nb - 1) {
        int h = t >> 6, k = t & 63;  // 256 == NH*ED
        float s = 0.f;
#pragma unroll
        for (int d = 0; d < HD; d++)
            s += W_edge[(h * HD + d) * ED + k] * __ldg(&a[h * 3 * HD + 2 * HD + d]);
        g_v[h * ED + k] = s;
    } else {
        int i = b * 256 + t;
        if (i <= n) g_cnt[i] = 0;
    }
}

// ---------------- launch 2: degree histogram ---------------------------------
__global__ void kern_hist(const int* __restrict__ ei, int n_edges) {
    int e = blockIdx.x * blockDim.x + threadIdx.x;
    if (e < n_edges) atomicAdd(&g_cnt[ei[n_edges + e]], 1);
}

// ---------------- launch 3: scan partials (proven r5 version) ----------------
__global__ void kern_scan_part(int n) {  // 256 thr x 4 items
    __shared__ int wsum[8];
    int t = threadIdx.x;
    int base = blockIdx.x * 1024 + t * 4;
    int v0 = (base + 0 < n) ? g_cnt[base + 0] : 0;
    int v1 = (base + 1 < n) ? g_cnt[base + 1] : 0;
    int v2 = (base + 2 < n) ? g_cnt[base + 2] : 0;
    int v3 = (base + 3 < n) ? g_cnt[base + 3] : 0;
    int sum = v0 + v1 + v2 + v3;
    int lane = t & 31, w = t >> 5;
    int inc = sum;
#pragma unroll
    for (int o = 1; o < 32; o <<= 1) {
        int x = __shfl_up_sync(0xffffffffu, inc, o);
        if (lane >= o) inc += x;
    }
    if (lane == 31) wsum[w] = inc;
    __syncthreads();
    if (t == 0) {
        int acc = 0;
        for (int i = 0; i < 8; i++) { int x = wsum[i]; wsum[i] = acc; acc += x; }
    }
    __syncthreads();
    int excl = inc - sum + wsum[w];
    if (base + 0 < n) g_off[base + 0] = excl;
    if (base + 1 < n) g_off[base + 1] = excl + v0;
    if (base + 2 < n) g_off[base + 2] = excl + v0 + v1;
    if (base + 3 < n) g_off[base + 3] = excl + v0 + v1 + v2;
    if (t == 255) g_part[blockIdx.x] = excl + sum;
}

// ---------------- launch 4 (profiled): h = X @ W^T f32x2 GEMM + s1/s2 -------
// FROZEN (57.7us reference point).
__global__ void __launch_bounds__(256, 2)
kern_gemm(const float* __restrict__ X, const float* __restrict__ W,
          const float* __restrict__ a, int n) {
    extern __shared__ float sm[];
    float* Ws = sm;               // [128 k][132 cols]
    float* At = sm + 128 * 132;  // [128 k][68 rows] (ull stride 34)
    int t = threadIdx.x;

    for (int i = t; i < ND * ND; i += 256) {
        int j = i >> 7, k = i & 127;
        Ws[k * 132 + j] = W[i];
    }
    int row0 = blockIdx.x * 64;
    for (int i = t; i < 64 * ND; i += 256) {
        int r = i >> 7, k = i & 127;
        int gr = row0 + r;
        At[k * 68 + r] = (gr < n) ? X[(size_t)gr * ND + k] : 0.f;
    }
    __syncthreads();

    int tx = t & 31, ty = t >> 5;
    ull acc[4][4];
#pragma unroll
    for (int p = 0; p < 4; p++)
#pragma unroll
        for (int c = 0; c < 4; c++) acc[p][c] = 0ULL;

    const ulonglong2* ab = (const ulonglong2*)At + ty * 2;  // + k*17 per step
    const float* wb = &Ws[tx * 4];

#pragma unroll 4
    for (int k = 0; k < ND; k++) {
        float4 wv = *(const float4*)(wb + k * 132);
        ull w0, w1, w2, w3;
        PACKDUP(w0, wv.x); PACKDUP(w1, wv.y); PACKDUP(w2, wv.z); PACKDUP(w3, wv.w);
        ulonglong2 A0 = ab[k * 17];      // row pairs 0,1
        ulonglong2 A1 = ab[k * 17 + 1];  // row pairs 2,3
        FMA2(acc[0][0], A0.x, w0); FMA2(acc[0][1], A0.x, w1);
        FMA2(acc[0][2], A0.x, w2); FMA2(acc[0][3], A0.x, w3);
        FMA2(acc[1][0], A0.y, w0); FMA2(acc[1][1], A0.y, w1);
        FMA2(acc[1][2], A0.y, w2); FMA2(acc[1][3], A0.y, w3);
        FMA2(acc[2][0], A1.x, w0); FMA2(acc[2][1], A1.x, w1);
        FMA2(acc[2][2], A1.x, w2); FMA2(acc[2][3], A1.x, w3);
        FMA2(acc[3][0], A1.y, w0); FMA2(acc[3][1], A1.y, w1);
        FMA2(acc[3][2], A1.y, w2); FMA2(acc[3][3], A1.y, w3);
    }

    int head = tx >> 3;
    int cbase = head * 3 * HD + ((tx * 4) & 31);
    float4 a1v = *(const float4*)&a[cbase];
    float4 a2v = *(const float4*)&a[cbase + HD];

#pragma unroll
    for (int p = 0; p < 4; p++) {
#pragma unroll
        for (int half = 0; half < 2; half++) {
            union { ull u; float2 f; } c0, c1, c2, c3;
            c0.u = acc[p][0]; c1.u = acc[p][1]; c2.u = acc[p][2]; c3.u = acc[p][3];
            float f0 = half ? c0.f.y : c0.f.x;
            float f1 = half ? c1.f.y : c1.f.x;
            float f2 = half ? c2.f.y : c2.f.x;
            float f3 = half ? c3.f.y : c3.f.x;
            int gr = row0 + ty * 8 + p * 2 + half;
            if (gr < n)
                *(float4*)&g_h[(size_t)gr * ND + tx * 4] = make_float4(f0, f1, f2, f3);
            float d1 = f0 * a1v.x + f1 * a1v.y + f2 * a1v.z + f3 * a1v.w;
            float d2 = f0 * a2v.x + f1 * a2v.y + f2 * a2v.z + f3 * a2v.w;
#pragma unroll
            for (int o = 4; o >= 1; o >>= 1) {
                d1 += __shfl_down_sync(0xffffffffu, d1, o, 8);
                d2 += __shfl_down_sync(0xffffffffu, d2, o, 8);
            }
            if ((tx & 7) == 0 && gr < n) {
                g_s1[gr * NH + head] = d1;
                g_s2[gr * NH + head] = d2;
            }
        }
    }
}

// ---------------- launch 5/6: scan top + add (proven r5 version) -------------
__global__ void kern_scan_top(int nb) {  // 1 block, 64 threads
    __shared__ int ws[2];
    int t = threadIdx.x;
    int v = (t < nb) ? g_part[t] : 0;
    int lane = t & 31, w = t >> 5;
    int inc = v;
#pragma unroll
    for (int o = 1; o < 32; o <<= 1) {
        int x = __shfl_up_sync(0xffffffffu, inc, o);
        if (lane >= o) inc += x;
    }
    if (lane == 31) ws[w] = inc;
    __syncthreads();
    int add = (w == 1) ? ws[0] : 0;
    if (t < nb) g_part[t] = inc - v + add;
}

__global__ void kern_scan_add(int n, int n_edges) {
    int i = blockIdx.x * blockDim.x + threadIdx.x;
    if (i < n) {
        int o = g_off[i] + g_part[i >> 10];
        g_off[i] = o;
        g_head[i] = o;
    }
    if (i == 0) g_off[n] = n_edges;
}

// ---------------- launch 7: att scores + CSR scatter -------------------------
__global__ void kern_p1s(const float* __restrict__ edgef, const int* __restrict__ ei,
                         int n_edges) {
    __shared__ float vs[NH * ED];
    vs[threadIdx.x] = g_v[threadIdx.x];
    __syncthreads();

    int gid = blockIdx.x * 256 + threadIdx.x;
    int edge = gid >> 4;
    int l = threadIdx.x & 15;
    if (edge >= n_edges) return;

    float4 ef = *(const float4*)&edgef[(size_t)edge * ED + 4 * l];
    float p[NH];
#pragma unroll
    for (int h = 0; h < NH; h++) {
        const float* v = &vs[h * ED + 4 * l];
        p[h] = ef.x * v[0] + ef.y * v[1] + ef.z * v[2] + ef.w * v[3];
    }
#pragma unroll
    for (int o = 8; o >= 1; o >>= 1)
#pragma unroll
        for (int h = 0; h < NH; h++) p[h] += __shfl_down_sync(0xffffffffu, p[h], o, 16);

    if (l == 0) {
        int src = ei[edge];
        int tgt = ei[n_edges + edge];
        float4 s1 = *(const float4*)&g_s1[src * NH];
        float4 s2 = *(const float4*)&g_s2[tgt * NH];
        float a0 = s1.x + s2.x + p[0];
        float a1 = s1.y + s2.y + p[1];
        float a2 = s1.z + s2.z + p[2];
        float a3 = s1.w + s2.w + p[3];
        float4 o4;
        o4.x = a0 > 0.f ? a0 : 0.2f * a0;
        o4.y = a1 > 0.f ? a1 : 0.2f * a1;
        o4.z = a2 > 0.f ? a2 : 0.2f * a2;
        o4.w = a3 > 0.f ? a3 : 0.2f * a3;
        *(float4*)&g_att[(size_t)edge * NH] = o4;
        int pos = atomicAdd(&g_head[tgt], 1);
        g_csr[pos] = make_int2(edge, src);
    }
}

// ---------------- launch 8: online softmax + aggregate (warp per node) -------
__global__ void kern_agg(float* __restrict__ out, int n_nodes, int n_edges) {
    int node = blockIdx.x * 8 + (threadIdx.x >> 5);
    int lane = threadIdx.x & 31;
    if (node >= n_nodes) return;
    int beg = g_off[node], end = g_off[node + 1];
    int deg = end - beg;
    int head = lane >> 3;

    // fused pass A+B: online (m, s) per lane, m init 0 (dense-softmax floor)
    float4 m = make_float4(0.f, 0.f, 0.f, 0.f);
    float4 s = make_float4(0.f, 0.f, 0.f, 0.f);
    for (int i = beg + lane; i < end; i += 32) {
        int e = g_csr[i].x;
        float4 v = *(const float4*)&g_att[(size_t)e * NH];
        float nm;
        nm = fmaxf(m.x, v.x); s.x = s.x * __expf(m.x - nm) + __expf(v.x - nm); m.x = nm;
        nm = fmaxf(m.y, v.y); s.y = s.y * __expf(m.y - nm) + __expf(v.y - nm); m.y = nm;
        nm = fmaxf(m.z, v.z); s.z = s.z * __expf(m.z - nm) + __expf(v.z - nm); m.z = nm;
        nm = fmaxf(m.w, v.w); s.w = s.w * __expf(m.w - nm) + __expf(v.w - nm); m.w = nm;
    }
    float4 M = m;
#pragma unroll
    for (int o = 16; o; o >>= 1) {
        M.x = fmaxf(M.x, __shfl_xor_sync(0xffffffffu, M.x, o));
        M.y = fmaxf(M.y, __shfl_xor_sync(0xffffffffu, M.y, o));
        M.z = fmaxf(M.z, __shfl_xor_sync(0xffffffffu, M.z, o));
        M.w = fmaxf(M.w, __shfl_xor_sync(0xffffffffu, M.w, o));
    }
    s.x *= __expf(m.x - M.x);
    s.y *= __expf(m.y - M.y);
    s.z *= __expf(m.z - M.z);
    s.w *= __expf(m.w - M.w);
#pragma unroll
    for (int o = 16; o; o >>= 1) {
        s.x += __shfl_xor_sync(0xffffffffu, s.x, o);
        s.y += __shfl_xor_sync(0xffffffffu, s.y, o);
        s.z += __shfl_xor_sync(0xffffffffu, s.z, o);
        s.w += __shfl_xor_sync(0xffffffffu, s.w, o);
    }
    float fE = (float)(n_edges - deg);
    float dx = s.x + fE * __expf(-M.x);
    float dy = s.y + fE * __expf(-M.y);
    float dz = s.z + fE * __expf(-M.z);
    float dw = s.w + fE * __expf(-M.w);
    float mh = (head == 0) ? M.x : (head == 1) ? M.y : (head == 2) ? M.z : M.w;
    float dh = (head == 0) ? dx : (head == 1) ? dy : (head == 2) ? dz : dw;
    float rd = 1.f / dh;

    // pass C: lane-parallel weights (8 edges x 4 heads per warp batch)
    float4 acc = make_float4(0.f, 0.f, 0.f, 0.f);
    for (int i = beg; i < end; i += 32) {
        int cnt = min(32, end - i);
        int2 es = g_csr[min(i + lane, end - 1)];
        for (int q = 0; q < cnt; q += 8) {
            int e_mine = __shfl_sync(0xffffffffu, es.x, q + (lane & 7));
            float w_mine =
                __expf(__ldg(&g_att[(size_t)e_mine * NH + head]) - mh) * rd;
            int jmax = min(8, cnt - q);
            int j = 0;
            for (; j + 4 <= jmax; j += 4) {
                float wj0 = __shfl_sync(0xffffffffu, w_mine, (lane & 24) + j + 0);
                float wj1 = __shfl_sync(0xffffffffu, w_mine, (lane & 24) + j + 1);
                float wj2 = __shfl_sync(0xffffffffu, w_mine, (lane & 24) + j + 2);
                float wj3 = __shfl_sync(0xffffffffu, w_mine, (lane & 24) + j + 3);
                int s0 = __shfl_sync(0xffffffffu, es.y, q + j + 0);
                int s1 = __shfl_sync(0xffffffffu, es.y, q + j + 1);
                int s2 = __shfl_sync(0xffffffffu, es.y, q + j + 2);
                int s3 = __shfl_sync(0xffffffffu, es.y, q + j + 3);
                float4 h0 = *(const float4*)&g_h[(size_t)s0 * ND + 4 * lane];
                float4 h1 = *(const float4*)&g_h[(size_t)s1 * ND + 4 * lane];
                float4 h2 = *(const float4*)&g_h[(size_t)s2 * ND + 4 * lane];
                float4 h3 = *(const float4*)&g_h[(size_t)s3 * ND + 4 * lane];
                acc.x += wj0 * h0.x + wj1 * h1.x + wj2 * h2.x + wj3 * h3.x;
                acc.y += wj0 * h0.y + wj1 * h1.y + wj2 * h2.y + wj3 * h3.y;
                acc.z += wj0 * h0.z + wj1 * h1.z + wj2 * h2.z + wj3 * h3.z;
                acc.w += wj0 * h0.w + wj1 * h1.w + wj2 * h2.w + wj3 * h3.w;
            }
            for (; j < jmax; j++) {
                float wj = __shfl_sync(0xffffffffu, w_mine, (lane & 24) + j);
                int sj = __shfl_sync(0xffffffffu, es.y, q + j);
                float4 hv = *(const float4*)&g_h[(size_t)sj * ND + 4 * lane];
                acc.x += wj * hv.x; acc.y += wj * hv.y;
                acc.z += wj * hv.z; acc.w += wj * hv.w;
            }
        }
    }
    *(float4*)&out[(size_t)node * ND + 4 * lane] = acc;
}

// ---------------- launch ------------------------------------------------------
extern "C" void kernel_launch(void* const* d_in, const int* in_sizes, int n_in,
                              void* d_out, int out_size) {
    const float* nodef = (const float*)d_in[0];
    const int* ei = (const int*)d_in[1];
    const float* edgef = (const float*)d_in[2];
    const float* W_node = (const float*)d_in[3];
    const float* W_edge = (const float*)d_in[4];
    const float* a = (const float*)d_in[5];
    float* out = (float*)d_out;

    int n_nodes = in_sizes[0] / ND;
    int n_edges = in_sizes[1] / 2;
    int nb = (n_nodes + 1023) >> 10;
    int Bc = (n_nodes + 1 + 255) / 256;

    kern_init<<<Bc + 1, 256>>>(W_edge, a, n_nodes);                 // 1
    kern_hist<<<(n_edges + 255) / 256, 256>>>(ei, n_edges);         // 2
    kern_scan_part<<<nb, 256>>>(n_nodes);                           // 3

    const int gemm_smem = (128 * 132 + 128 * 68) * (int)sizeof(float);  // 100KB
    cudaFuncSetAttribute(kern_gemm, cudaFuncAttributeMaxDynamicSharedMemorySize,
                         gemm_smem);
    kern_gemm<<<(n_nodes + 63) / 64, 256, gemm_smem>>>(nodef, W_node, a, n_nodes);  // 4

    kern_scan_top<<<1, 64>>>(nb);                                   // 5
    kern_scan_add<<<(n_nodes + 255) / 256, 256>>>(n_nodes, n_edges);  // 6
    kern_p1s<<<(n_edges + 15) / 16, 256>>>(edgef, ei, n_edges);     // 7
    kern_agg<<<(n_nodes + 7) / 8, 256>>>(out, n_nodes, n_edges);    // 8
}

// round 8
// speedup vs baseline: 1.4017x; 1.0259x over previous
#include <cuda_runtime.h>
#include <cstdint>

#define ND 128
#define ED 64
#define NH 4
#define HD 32
#define MAX_NODES 50000
#define MAX_EDGES 600000

typedef unsigned long long ull;

// ---------------- scratch (static device globals) ---------------------------
__device__ __align__(16) float g_h[MAX_NODES * ND];      // projected nodes
__device__ __align__(16) float g_s1[MAX_NODES * NH];     // h . a[:, 0:32]
__device__ __align__(16) float g_s2[MAX_NODES * NH];     // h . a[:, 32:64]
__device__ __align__(16) float g_att[MAX_EDGES * NH];    // exp(leaky(att))
__device__ __align__(16) float g_denom[MAX_NODES * NH];  // sum of exp per node
__device__ __align__(16) float g_v[NH * ED];             // folded edge attn vec
__device__ int g_cnt[MAX_NODES + 1];                     // degree histogram
__device__ int g_off[MAX_NODES + 1];                     // CSR row offsets
__device__ int g_head[MAX_NODES];                        // scatter cursors
__device__ __align__(8) int2 g_csr[MAX_EDGES];           // {edge id, src} per tgt
__device__ int g_part[64];                               // scan partials

#define FMA2(d, a, b) \
    asm("fma.rn.f32x2 %0, %1, %2, %0;" : "+l"(d) : "l"(a), "l"(b))
#define PACKDUP(d, f) \
    asm("mov.b64 %0, {%1, %1};" : "=l"(d) : "r"(__float_as_uint(f)))

// ---------------- launch 1: zero cnt/denom + fold W_edge into attn vec ------
__global__ void kern_init(const float* __restrict__ W_edge,
                          const float* __restrict__ a, int n, int Bc) {
    int b = blockIdx.x, nb = gridDim.x, t = threadIdx.x;
    if (b == nb - 1) {
        int h = t >> 6, k = t & 63;  // 256 == NH*ED
        float s = 0.f;
#pragma unroll
        for (int d = 0; d < HD; d++)
            s += W_edge[(h * HD + d) * ED + k] * __ldg(&a[h * 3 * HD + 2 * HD + d]);
        g_v[h * ED + k] = s;
    } else if (b < Bc) {
        int i = b * 256 + t;
        if (i <= n) g_cnt[i] = 0;
    } else {
        int i = (b - Bc) * 256 + t;
        if (i < n * NH) g_denom[i] = 0.f;
    }
}

// ---------------- launch 2: degree histogram ---------------------------------
__global__ void kern_hist(const int* __restrict__ ei, int n_edges) {
    int e = blockIdx.x * blockDim.x + threadIdx.x;
    if (e < n_edges) atomicAdd(&g_cnt[ei[n_edges + e]], 1);
}

// ---------------- launch 3: scan partials (proven) ---------------------------
__global__ void kern_scan_part(int n) {  // 256 thr x 4 items
    __shared__ int wsum[8];
    int t = threadIdx.x;
    int base = blockIdx.x * 1024 + t * 4;
    int v0 = (base + 0 < n) ? g_cnt[base + 0] : 0;
    int v1 = (base + 1 < n) ? g_cnt[base + 1] : 0;
    int v2 = (base + 2 < n) ? g_cnt[base + 2] : 0;
    int v3 = (base + 3 < n) ? g_cnt[base + 3] : 0;
    int sum = v0 + v1 + v2 + v3;
    int lane = t & 31, w = t >> 5;
    int inc = sum;
#pragma unroll
    for (int o = 1; o < 32; o <<= 1) {
        int x = __shfl_up_sync(0xffffffffu, inc, o);
        if (lane >= o) inc += x;
    }
    if (lane == 31) wsum[w] = inc;
    __syncthreads();
    if (t == 0) {
        int acc = 0;
        for (int i = 0; i < 8; i++) { int x = wsum[i]; wsum[i] = acc; acc += x; }
    }
    __syncthreads();
    int excl = inc - sum + wsum[w];
    if (base + 0 < n) g_off[base + 0] = excl;
    if (base + 1 < n) g_off[base + 1] = excl + v0;
    if (base + 2 < n) g_off[base + 2] = excl + v0 + v1;
    if (base + 3 < n) g_off[base + 3] = excl + v0 + v1 + v2;
    if (t == 255) g_part[blockIdx.x] = excl + sum;
}

// ---------------- launch 4 (profiled): h = X @ W^T f32x2 GEMM + s1/s2 -------
// k-chunked (2 x 64) to halve smem -> 4 CTAs/SM. Same FMA schedule as r5.
__global__ void __launch_bounds__(256, 4)
kern_gemm(const float* __restrict__ X, const float* __restrict__ W,
          const float* __restrict__ a, int n) {
    extern __shared__ float sm[];
    float* Ws = sm;              // [64 k][132 cols]
    float* At = sm + 64 * 132;  // [64 k][68 rows] (ull stride 34)
    int t = threadIdx.x;
    int row0 = blockIdx.x * 64;

    int tx = t & 31, ty = t >> 5;
    ull acc[4][4];
#pragma unroll
    for (int p = 0; p < 4; p++)
#pragma unroll
        for (int c = 0; c < 4; c++) acc[p][c] = 0ULL;

    const ulonglong2* ab = (const ulonglong2*)At + ty * 2;  // + k*17 per step
    const float* wb = &Ws[tx * 4];

    for (int kc = 0; kc < ND; kc += 64) {
        __syncthreads();
        for (int i = t; i < 64 * ND; i += 256) {  // W chunk: all j, kk in [0,64)
            int j = i >> 6, kk = i & 63;
            Ws[kk * 132 + j] = W[j * ND + kc + kk];
        }
        for (int i = t; i < 64 * 64; i += 256) {  // A chunk
            int r = i >> 6, kk = i & 63;
            int gr = row0 + r;
            At[kk * 68 + r] = (gr < n) ? X[(size_t)gr * ND + kc + kk] : 0.f;
        }
        __syncthreads();

#pragma unroll 4
        for (int k = 0; k < 64; k++) {
            float4 wv = *(const float4*)(wb + k * 132);
            ull w0, w1, w2, w3;
            PACKDUP(w0, wv.x); PACKDUP(w1, wv.y);
            PACKDUP(w2, wv.z); PACKDUP(w3, wv.w);
            ulonglong2 A0 = ab[k * 17];      // row pairs 0,1
            ulonglong2 A1 = ab[k * 17 + 1];  // row pairs 2,3
            FMA2(acc[0][0], A0.x, w0); FMA2(acc[0][1], A0.x, w1);
            FMA2(acc[0][2], A0.x, w2); FMA2(acc[0][3], A0.x, w3);
            FMA2(acc[1][0], A0.y, w0); FMA2(acc[1][1], A0.y, w1);
            FMA2(acc[1][2], A0.y, w2); FMA2(acc[1][3], A0.y, w3);
            FMA2(acc[2][0], A1.x, w0); FMA2(acc[2][1], A1.x, w1);
            FMA2(acc[2][2], A1.x, w2); FMA2(acc[2][3], A1.x, w3);
            FMA2(acc[3][0], A1.y, w0); FMA2(acc[3][1], A1.y, w1);
            FMA2(acc[3][2], A1.y, w2); FMA2(acc[3][3], A1.y, w3);
        }
    }

    int head = tx >> 3;
    int cbase = head * 3 * HD + ((tx * 4) & 31);
    float4 a1v = *(const float4*)&a[cbase];
    float4 a2v = *(const float4*)&a[cbase + HD];

#pragma unroll
    for (int p = 0; p < 4; p++) {
#pragma unroll
        for (int half = 0; half < 2; half++) {
            union { ull u; float2 f; } c0, c1, c2, c3;
            c0.u = acc[p][0]; c1.u = acc[p][1]; c2.u = acc[p][2]; c3.u = acc[p][3];
            float f0 = half ? c0.f.y : c0.f.x;
            float f1 = half ? c1.f.y : c1.f.x;
            float f2 = half ? c2.f.y : c2.f.x;
            float f3 = half ? c3.f.y : c3.f.x;
            int gr = row0 + ty * 8 + p * 2 + half;
            if (gr < n)
                *(float4*)&g_h[(size_t)gr * ND + tx * 4] = make_float4(f0, f1, f2, f3);
            float d1 = f0 * a1v.x + f1 * a1v.y + f2 * a1v.z + f3 * a1v.w;
            float d2 = f0 * a2v.x + f1 * a2v.y + f2 * a2v.z + f3 * a2v.w;
#pragma unroll
            for (int o = 4; o >= 1; o >>= 1) {
                d1 += __shfl_down_sync(0xffffffffu, d1, o, 8);
                d2 += __shfl_down_sync(0xffffffffu, d2, o, 8);
            }
            if ((tx & 7) == 0 && gr < n) {
                g_s1[gr * NH + head] = d1;
                g_s2[gr * NH + head] = d2;
            }
        }
    }
}

// ---------------- launch 5/6: scan top + add (proven) ------------------------
__global__ void kern_scan_top(int nb) {  // 1 block, 64 threads
    __shared__ int ws[2];
    int t = threadIdx.x;
    int v = (t < nb) ? g_part[t] : 0;
    int lane = t & 31, w = t >> 5;
    int inc = v;
#pragma unroll
    for (int o = 1; o < 32; o <<= 1) {
        int x = __shfl_up_sync(0xffffffffu, inc, o);
        if (lane >= o) inc += x;
    }
    if (lane == 31) ws[w] = inc;
    __syncthreads();
    int add = (w == 1) ? ws[0] : 0;
    if (t < nb) g_part[t] = inc - v + add;
}

__global__ void kern_scan_add(int n, int n_edges) {
    int i = blockIdx.x * blockDim.x + threadIdx.x;
    if (i < n) {
        int o = g_off[i] + g_part[i >> 10];
        g_off[i] = o;
        g_head[i] = o;
    }
    if (i == 0) g_off[n] = n_edges;
}

// ---------------- launch 7: exp(att) + denom atomics + CSR scatter -----------
// Softmax shift-invariance with m=0: w = exp(att) / [sum exp(att) + (E-deg)].
// att_max ~ 50 << 88 -> exp never overflows fp32.
__global__ void kern_p1s(const float* __restrict__ edgef, const int* __restrict__ ei,
                         int n_edges) {
    __shared__ float vs[NH * ED];
    vs[threadIdx.x] = g_v[threadIdx.x];
    __syncthreads();

    int gid = blockIdx.x * 256 + threadIdx.x;
    int edge = gid >> 4;
    int l = threadIdx.x & 15;
    if (edge >= n_edges) return;

    float4 ef = *(const float4*)&edgef[(size_t)edge * ED + 4 * l];
    float p[NH];
#pragma unroll
    for (int h = 0; h < NH; h++) {
        const float* v = &vs[h * ED + 4 * l];
        p[h] = ef.x * v[0] + ef.y * v[1] + ef.z * v[2] + ef.w * v[3];
    }
#pragma unroll
    for (int o = 8; o >= 1; o >>= 1)
#pragma unroll
        for (int h = 0; h < NH; h++) p[h] += __shfl_down_sync(0xffffffffu, p[h], o, 16);

    if (l == 0) {
        int src = ei[edge];
        int tgt = ei[n_edges + edge];
        float4 s1 = *(const float4*)&g_s1[src * NH];
        float4 s2 = *(const float4*)&g_s2[tgt * NH];
        float a0 = s1.x + s2.x + p[0];
        float a1 = s1.y + s2.y + p[1];
        float a2 = s1.z + s2.z + p[2];
        float a3 = s1.w + s2.w + p[3];
        float4 e4;
        e4.x = __expf(a0 > 0.f ? a0 : 0.2f * a0);
        e4.y = __expf(a1 > 0.f ? a1 : 0.2f * a1);
        e4.z = __expf(a2 > 0.f ? a2 : 0.2f * a2);
        e4.w = __expf(a3 > 0.f ? a3 : 0.2f * a3);
        *(float4*)&g_att[(size_t)edge * NH] = e4;
        atomicAdd(&g_denom[tgt * NH + 0], e4.x);
        atomicAdd(&g_denom[tgt * NH + 1], e4.y);
        atomicAdd(&g_denom[tgt * NH + 2], e4.z);
        atomicAdd(&g_denom[tgt * NH + 3], e4.w);
        int pos = atomicAdd(&g_head[tgt], 1);
        g_csr[pos] = make_int2(edge, src);
    }
}

// ---------------- launch 8: pure gather-aggregate (warp per node) ------------
__global__ void kern_agg(float* __restrict__ out, int n_nodes, int n_edges) {
    int node = blockIdx.x * 8 + (threadIdx.x >> 5);
    int lane = threadIdx.x & 31;
    if (node >= n_nodes) return;
    int beg = g_off[node], end = g_off[node + 1];
    int deg = end - beg;
    int head = lane >> 3;

    float dh = __ldg(&g_denom[node * NH + head]) + (float)(n_edges - deg);
    float rd = 1.f / dh;

    float4 acc = make_float4(0.f, 0.f, 0.f, 0.f);
    for (int i = beg; i < end; i += 32) {
        int cnt = min(32, end - i);
        int2 es = g_csr[min(i + lane, end - 1)];
        for (int q = 0; q < cnt; q += 8) {
            // producer lane (hh*8+jj) loads weight of edge q+jj, head hh
            int e_mine = __shfl_sync(0xffffffffu, es.x, q + (lane & 7));
            float w_mine = __ldg(&g_att[(size_t)e_mine * NH + head]) * rd;
            int jmax = min(8, cnt - q);
            int j = 0;
            for (; j + 4 <= jmax; j += 4) {
                float wj0 = __shfl_sync(0xffffffffu, w_mine, (lane & 24) + j + 0);
                float wj1 = __shfl_sync(0xffffffffu, w_mine, (lane & 24) + j + 1);
                float wj2 = __shfl_sync(0xffffffffu, w_mine, (lane & 24) + j + 2);
                float wj3 = __shfl_sync(0xffffffffu, w_mine, (lane & 24) + j + 3);
                int s0 = __shfl_sync(0xffffffffu, es.y, q + j + 0);
                int s1 = __shfl_sync(0xffffffffu, es.y, q + j + 1);
                int s2 = __shfl_sync(0xffffffffu, es.y, q + j + 2);
                int s3 = __shfl_sync(0xffffffffu, es.y, q + j + 3);
                float4 h0 = *(const float4*)&g_h[(size_t)s0 * ND + 4 * lane];
                float4 h1 = *(const float4*)&g_h[(size_t)s1 * ND + 4 * lane];
                float4 h2 = *(const float4*)&g_h[(size_t)s2 * ND + 4 * lane];
                float4 h3 = *(const float4*)&g_h[(size_t)s3 * ND + 4 * lane];
                acc.x += wj0 * h0.x + wj1 * h1.x + wj2 * h2.x + wj3 * h3.x;
                acc.y += wj0 * h0.y + wj1 * h1.y + wj2 * h2.y + wj3 * h3.y;
                acc.z += wj0 * h0.z + wj1 * h1.z + wj2 * h2.z + wj3 * h3.z;
                acc.w += wj0 * h0.w + wj1 * h1.w + wj2 * h2.w + wj3 * h3.w;
            }
            for (; j < jmax; j++) {
                float wj = __shfl_sync(0xffffffffu, w_mine, (lane & 24) + j);
                int sj = __shfl_sync(0xffffffffu, es.y, q + j);
                float4 hv = *(const float4*)&g_h[(size_t)sj * ND + 4 * lane];
                acc.x += wj * hv.x; acc.y += wj * hv.y;
                acc.z += wj * hv.z; acc.w += wj * hv.w;
            }
        }
    }
    *(float4*)&out[(size_t)node * ND + 4 * lane] = acc;
}

// ---------------- launch ------------------------------------------------------
extern "C" void kernel_launch(void* const* d_in, const int* in_sizes, int n_in,
                              void* d_out, int out_size) {
    const float* nodef = (const float*)d_in[0];
    const int* ei = (const int*)d_in[1];
    const float* edgef = (const float*)d_in[2];
    const float* W_node = (const float*)d_in[3];
    const float* W_edge = (const float*)d_in[4];
    const float* a = (const float*)d_in[5];
    float* out = (float*)d_out;

    int n_nodes = in_sizes[0] / ND;
    int n_edges = in_sizes[1] / 2;
    int nb = (n_nodes + 1023) >> 10;
    int Bc = (n_nodes + 1 + 255) / 256;
    int Bd = (n_nodes * NH + 255) / 256;

    kern_init<<<Bc + Bd + 1, 256>>>(W_edge, a, n_nodes, Bc);        // 1
    kern_hist<<<(n_edges + 255) / 256, 256>>>(ei, n_edges);         // 2
    kern_scan_part<<<nb, 256>>>(n_nodes);                           // 3

    const int gemm_smem = (64 * 132 + 64 * 68) * (int)sizeof(float);  // 51.2KB
    cudaFuncSetAttribute(kern_gemm, cudaFuncAttributeMaxDynamicSharedMemorySize,
                         gemm_smem);
    kern_gemm<<<(n_nodes + 63) / 64, 256, gemm_smem>>>(nodef, W_node, a, n_nodes);  // 4

    kern_scan_top<<<1, 64>>>(nb);                                   // 5
    kern_scan_add<<<(n_nodes + 255) / 256, 256>>>(n_nodes, n_edges);  // 6
    kern_p1s<<<(n_edges + 15) / 16, 256>>>(edgef, ei, n_edges);     // 7
    kern_agg<<<(n_nodes + 7) / 8, 256>>>(out, n_nodes, n_edges);    // 8
}